// round 5
// baseline (speedup 1.0000x reference)
#include <cuda_runtime.h>
#include <math.h>

#define N_PTS 12288
#define DIM   128
#define BI    32
#define BJ    64
#define EPSF  1e-7f
#define MAXN  (1.0f - 1e-3f)
#define NEG_SLOPE 0.2f

// Scratch (device globals — no allocation allowed)
__device__ float g_xt[N_PTS * DIM];   // logmap0(x), 6.3 MB (L2-resident)
__device__ float g_wh1[N_PTS];
__device__ float g_wh2[N_PTS];

// ---------------------------------------------------------------------------
// Kernel 1: per-row logmap0 + the two projections  wh1 = xt@a[:D], wh2 = xt@a[D:]
// One block per row, 128 threads (one per dim).
// ---------------------------------------------------------------------------
__global__ void prep_kernel(const float* __restrict__ x, const float* __restrict__ a) {
    int i = blockIdx.x;
    int d = threadIdx.x;
    float xv = x[(size_t)i * DIM + d];
    float s0 = xv * xv;
    float s1 = xv * a[d];
    float s2 = xv * a[DIM + d];
#pragma unroll
    for (int o = 16; o > 0; o >>= 1) {
        s0 += __shfl_down_sync(0xffffffffu, s0, o);
        s1 += __shfl_down_sync(0xffffffffu, s1, o);
        s2 += __shfl_down_sync(0xffffffffu, s2, o);
    }
    __shared__ float sm0[4], sm1[4], sm2[4];
    __shared__ float sscale;
    int w = d >> 5, l = d & 31;
    if (l == 0) { sm0[w] = s0; sm1[w] = s1; sm2[w] = s2; }
    __syncthreads();
    if (d == 0) {
        float t0 = sm0[0] + sm0[1] + sm0[2] + sm0[3];
        float t1 = sm1[0] + sm1[1] + sm1[2] + sm1[3];
        float t2 = sm2[0] + sm2[1] + sm2[2] + sm2[3];
        float n  = sqrtf(t0);
        float nc = fminf(fmaxf(n, EPSF), 1.0f - EPSF);   // clip(norm, EPS, 1-EPS)
        float sc = atanhf(nc) / nc;                      // arctanh(nc)/nc
        sscale   = sc;
        g_wh1[i] = sc * t1;
        g_wh2[i] = sc * t2;
    }
    __syncthreads();
    g_xt[(size_t)i * DIM + d] = xv * sscale;
}

// ---------------------------------------------------------------------------
// Kernel 2: fused masked-softmax attention (flash-style, online softmax).
// CTA: BI=32 rows x all N columns, tiled BJ=64. 256 threads.
// Phase 1: thread (p_row = tid/8, p_jo = tid%8) builds scores/p for its row.
// Phase 2: thread (ry = tid/32, cx = tid%32) does a 4x4 register-blocked
//          rank-BJ update: acc[r][c] += p[jj][row] * xt[jj][dim].
// ---------------------------------------------------------------------------
__global__ __launch_bounds__(256, 3) void attn_kernel(const int* __restrict__ adj,
                                                      float* __restrict__ out) {
    __shared__ __align__(16) float xt_s[BJ][DIM];  // 32 KB
    __shared__ __align__(16) float pT[BJ][36];     // 9 KB, padded: p transposed [jj][row]
    __shared__ float m_s[BI], l_s[BI], r_s[BI];

    int tid = threadIdx.x;
    int i0  = blockIdx.x * BI;
    int p_row = tid >> 3;      // 0..31
    int p_jo  = tid & 7;       // 0..7
    int cx = tid & 31;         // dims cx*4..+3
    int ry = tid >> 5;         // rows ry*4..+3

    float acc[4][4];
#pragma unroll
    for (int r = 0; r < 4; r++)
#pragma unroll
        for (int c = 0; c < 4; c++) acc[r][c] = 0.f;

    if (tid < BI) { m_s[tid] = -INFINITY; l_s[tid] = 0.f; }

    float wh1 = g_wh1[i0 + p_row];
    const int* adjrow = adj + (size_t)(i0 + p_row) * N_PTS;

    __syncthreads();

    for (int j0 = 0; j0 < N_PTS; j0 += BJ) {
        // ---- load x_tan tile (from L2) ----
#pragma unroll
        for (int s = 0; s < (BJ * DIM / 4) / 256; s++) {   // 8 float4 per thread
            int slot = tid + s * 256;
            int jj = slot >> 5;
            int c4 = (slot & 31) << 2;
            *(float4*)&xt_s[jj][c4] =
                *(const float4*)&g_xt[(size_t)(j0 + jj) * DIM + c4];
        }

        // ---- phase 1: scores, tile max ----
        float e[8];
        float tmax = -INFINITY;
#pragma unroll
        for (int k = 0; k < 8; k++) {
            int j = j0 + p_jo + (k << 3);
            float t  = wh1 + g_wh2[j];
            float sc = t >= 0.f ? t : NEG_SLOPE * t;       // leaky_relu(t, 0.2)
            e[k] = (adjrow[j] > 0) ? sc : -INFINITY;       // mask
            tmax = fmaxf(tmax, e[k]);
        }
        tmax = fmaxf(tmax, __shfl_xor_sync(0xffffffffu, tmax, 1));
        tmax = fmaxf(tmax, __shfl_xor_sync(0xffffffffu, tmax, 2));
        tmax = fmaxf(tmax, __shfl_xor_sync(0xffffffffu, tmax, 4));
        if (p_jo == 0) {
            float mo = m_s[p_row];
            float mn = fmaxf(mo, tmax);
            r_s[p_row] = (mn == -INFINITY) ? 1.f
                       : ((mo == -INFINITY) ? 0.f : __expf(mo - mn));
            m_s[p_row] = mn;
        }
        __syncthreads();

        // ---- p = exp(e - m), stage transposed; update l; rescale acc ----
        float mn = m_s[p_row];
        float lsum = 0.f;
#pragma unroll
        for (int k = 0; k < 8; k++) {
            float p = (mn == -INFINITY) ? 0.f : __expf(e[k] - mn);  // exp(-inf)=0 for masked
            pT[p_jo + (k << 3)][p_row] = p;                         // conflict-free banks
            lsum += p;
        }
        lsum += __shfl_xor_sync(0xffffffffu, lsum, 1);
        lsum += __shfl_xor_sync(0xffffffffu, lsum, 2);
        lsum += __shfl_xor_sync(0xffffffffu, lsum, 4);
        if (p_jo == 0) l_s[p_row] = l_s[p_row] * r_s[p_row] + lsum;

#pragma unroll
        for (int r = 0; r < 4; r++) {
            float rv = r_s[(ry << 2) + r];
            acc[r][0] *= rv; acc[r][1] *= rv; acc[r][2] *= rv; acc[r][3] *= rv;
        }
        __syncthreads();

        // ---- phase 2: rank-BJ update (register-blocked 4x4) ----
#pragma unroll 8
        for (int jj = 0; jj < BJ; jj++) {
            float4 pv = *(const float4*)&pT[jj][ry << 2];   // broadcast within warp
            float4 xv = *(const float4*)&xt_s[jj][cx << 2]; // conflict-free
            acc[0][0] += pv.x * xv.x; acc[0][1] += pv.x * xv.y;
            acc[0][2] += pv.x * xv.z; acc[0][3] += pv.x * xv.w;
            acc[1][0] += pv.y * xv.x; acc[1][1] += pv.y * xv.y;
            acc[1][2] += pv.y * xv.z; acc[1][3] += pv.y * xv.w;
            acc[2][0] += pv.z * xv.x; acc[2][1] += pv.z * xv.y;
            acc[2][2] += pv.z * xv.z; acc[2][3] += pv.z * xv.w;
            acc[3][0] += pv.w * xv.x; acc[3][1] += pv.w * xv.y;
            acc[3][2] += pv.w * xv.z; acc[3][3] += pv.w * xv.w;
        }
        __syncthreads();
    }

    // ---- epilogue: v = acc/l; expmap0; proj ----
#pragma unroll
    for (int r = 0; r < 4; r++) {
        int row = (ry << 2) + r;
        float linv = 1.f / l_s[row];
        float v0 = acc[r][0] * linv, v1 = acc[r][1] * linv;
        float v2 = acc[r][2] * linv, v3 = acc[r][3] * linv;
        float part = v0 * v0 + v1 * v1 + v2 * v2 + v3 * v3;
#pragma unroll
        for (int o = 16; o > 0; o >>= 1) part += __shfl_xor_sync(0xffffffffu, part, o);
        float n  = sqrtf(part);
        float nc = fmaxf(n, EPSF);
        float sc = tanhf(nc) / nc;        // expmap0 scale
        float ny = fmaxf(sc * n, EPSF);   // ||y|| (clipped low)
        float f  = (ny > MAXN) ? sc * (MAXN / ny) : sc;   // proj
        float4 o4 = make_float4(v0 * f, v1 * f, v2 * f, v3 * f);
        *(float4*)&out[(size_t)(i0 + row) * DIM + (cx << 2)] = o4;
    }
}

// ---------------------------------------------------------------------------
extern "C" void kernel_launch(void* const* d_in, const int* in_sizes, int n_in,
                              void* d_out, int out_size) {
    // Identify inputs by element count (robust to metadata ordering):
    // x: 12288*128 = 1572864 f32, adj: 12288*12288 = 150994944 i32, a: 256 f32
    const float* x = nullptr;
    const int*   adj = nullptr;
    const float* a = nullptr;
    for (int i = 0; i < n_in; i++) {
        if (in_sizes[i] == N_PTS * DIM)      x   = (const float*)d_in[i];
        else if (in_sizes[i] == 2 * DIM)     a   = (const float*)d_in[i];
        else                                 adj = (const int*)d_in[i];
    }
    float* out = (float*)d_out;

    prep_kernel<<<N_PTS, DIM>>>(x, a);
    attn_kernel<<<N_PTS / BI, 256>>>(adj, out);
}